// round 9
// baseline (speedup 1.0000x reference)
#include <cuda_runtime.h>
#include <math.h>

#define NB    4      // batch
#define S     363    // sinogram length / recon grid
#define A     180    // angles
#define ASP   3      // backproject angle splits
#define A3    60     // angles per split
#define W     256    // output size
#define RP    364    // table row entries, k in [0,363]
#define NSTR  (A * RP)               // per-batch stride in float2

// tab[na][k] = (mid_k, delta_k), delta_k = p[k]-p[k-1], mid_k = p[k-1]+0.5*delta
// with p[-1] = p[363] = 0. Interp at q (=pos+1, floor k): mid + (w-0.5)*delta.
__device__ float2 g_tab[NB * NSTR];
// angle-split partial sums, layout matches out: [split][n][yy][xx]
__device__ float g_part[ASP][NB * W * W];

// One block per (n, a) column, 96 threads. Thread t computes outputs 4t..4t+3
// by sweeping the padded input as float4s; all tap weights are compile-time
// immediates.  p[s] = sum_k x[k] * g(k-s), g(0)=0.5, g(+-d)=-2/(pi d)^2 (d odd).
__global__ __launch_bounds__(96) void ramp_filter_kernel(const float* __restrict__ x) {
    const int na = blockIdx.x;
    const int n  = na / A;
    const int a  = na - n * A;

    __shared__ float4 xs4[273];   // 1092 floats: zeros[0,364) | x[364,727) | zeros
    __shared__ float  ps[S + 2];  // p[-1..363], zero ends

    float* xs = (float*)xs4;
    const int t = threadIdx.x;

    for (int i = t; i < 1092; i += 96) xs[i] = 0.0f;
    if (t == 0) ps[0] = 0.0f;
    if (t == 1) ps[364] = 0.0f;
    __syncthreads();
    // input layout: [n][1][s][a], a fastest
    for (int s = t; s < S; s += 96)
        xs[364 + s] = x[(n * S + s) * A + a];
    __syncthreads();

    if (t < 91) {
        float acc0 = 0.f, acc1 = 0.f, acc2 = 0.f, acc3 = 0.f;
        #pragma unroll
        for (int m = 0; m <= 182; ++m) {
            const float4 X = xs4[t + m];
            #pragma unroll
            for (int c = 0; c < 4; ++c) {
                const float Xc = (c == 0) ? X.x : (c == 1) ? X.y : (c == 2) ? X.z : X.w;
                #pragma unroll
                for (int r = 0; r < 4; ++r) {
                    const int d = 4 * m + c - r - 364;
                    float* accp = (r == 0) ? &acc0 : (r == 1) ? &acc1 : (r == 2) ? &acc2 : &acc3;
                    if (d & 1) {
                        const float h = -2.0f / ((float)(M_PI * M_PI) * (float)d * (float)d);
                        *accp = fmaf(Xc, h, *accp);
                    } else if (d == 0) {
                        *accp = fmaf(Xc, 0.5f, *accp);
                    }
                }
            }
        }
        const int s0 = 4 * t;
        ps[1 + s0] = acc0;
        if (s0 + 1 < S) ps[2 + s0] = acc1;
        if (s0 + 2 < S) ps[3 + s0] = acc2;
        if (s0 + 3 < S) ps[4 + s0] = acc3;
    }
    __syncthreads();

    float2* gr = g_tab + (size_t)na * RP;
    for (int k = t; k < RP; k += 96) {      // k in [0, 363]
        const float p0 = ps[k];             // p[k-1]
        const float p1 = ps[k + 1];         // p[k]
        const float d  = p1 - p0;
        gr[k] = make_float2(fmaf(0.5f, d, p0), d);
    }
}

#define CH 2                     // angles per pipeline chunk (60/2 = 30, even)
#define NCHUNK (A3 / CH)
#define MAGICF 12582912.0f       // 2^23 + 2^22
#define MAGICI 0x4B400000

// grid (W, ASP): one block = one output row x one angle-split; all 4 batches
// fused per thread. qp = xf*cos - yf*sin + 181.5; k = round(qp) via magic,
// t = qp - k in [-0.5,0.5]; value = mid[k] + t*delta[k].
__global__ __launch_bounds__(256) void backproject_kernel() {
    const int yy = blockIdx.x;
    const int hf = blockIdx.y;
    const int xx = threadIdx.x;
    const int abase = hf * A3;

    __shared__ float2 scb[A3];   // (cos, 181.5 - yf*sin) for angle abase+t

    const float yf = (float)(yy - 128);
    if (threadIdx.x < A3) {
        float sn, cs;
        sincosf((float)(abase + threadIdx.x) * (float)(M_PI / 180.0), &sn, &cs);
        scb[threadIdx.x] = make_float2(cs, fmaf(-yf, sn, 181.5f));
    }
    __syncthreads();

    const float xf = (float)(xx - 128);
    const float2* __restrict__ tb = g_tab + (size_t)abase * RP;

    float accm0 = 0.f, accm1 = 0.f, accm2 = 0.f, accm3 = 0.f;
    float accd0 = 0.f, accd1 = 0.f, accd2 = 0.f, accd3 = 0.f;

    float2 va[CH * NB], vb[CH * NB];
    float  wa[CH], wb[CH];

    #define LOADC(c, vv, ww)                                                  \
        {                                                                     \
            const int a0 = (c) * CH;                                          \
            _Pragma("unroll")                                                 \
            for (int k = 0; k < CH; ++k) {                                    \
                const float2 cb = scb[a0 + k];                                \
                const float qp = fmaf(xf, cb.x, cb.y);   /* q - 0.5 */        \
                const float f  = qp + MAGICF;                                 \
                const float il = f - MAGICF;             /* round(qp) */      \
                ww[k] = qp - il;                         /* in [-.5,.5] */    \
                const int i = __float_as_int(f) - MAGICI;                     \
                const float2* p = tb + (a0 + k) * RP + i;                     \
                _Pragma("unroll")                                             \
                for (int n = 0; n < NB; ++n)                                  \
                    vv[k * NB + n] = __ldg(p + n * NSTR);                     \
            }                                                                 \
        }

    #define ACCC(vv, ww)                                                      \
        {                                                                     \
            _Pragma("unroll")                                                 \
            for (int k = 0; k < CH; ++k) {                                    \
                accm0 += vv[k * NB + 0].x;                                    \
                accd0 = fmaf(ww[k], vv[k * NB + 0].y, accd0);                 \
                accm1 += vv[k * NB + 1].x;                                    \
                accd1 = fmaf(ww[k], vv[k * NB + 1].y, accd1);                 \
                accm2 += vv[k * NB + 2].x;                                    \
                accd2 = fmaf(ww[k], vv[k * NB + 2].y, accd2);                 \
                accm3 += vv[k * NB + 3].x;                                    \
                accd3 = fmaf(ww[k], vv[k * NB + 3].y, accd3);                 \
            }                                                                 \
        }

    LOADC(0, va, wa)
    LOADC(1, vb, wb)
    #pragma unroll 1
    for (int c = 0; c + 2 < NCHUNK; c += 2) {
        ACCC(va, wa)
        LOADC(c + 2, va, wa)
        ACCC(vb, wb)
        LOADC(c + 3, vb, wb)
    }
    ACCC(va, wa)
    ACCC(vb, wb)

    #undef LOADC
    #undef ACCC

    float* o = g_part[hf] + (size_t)yy * W + xx;
    o[0 * W * W] = accm0 + accd0;
    o[1 * W * W] = accm1 + accd1;
    o[2 * W * W] = accm2 + accd2;
    o[3 * W * W] = accm3 + accd3;
}

// out = (part0 + part1 + part2) * pi/360, fully coalesced float4.
__global__ __launch_bounds__(256) void combine_kernel(float* __restrict__ out) {
    const int i = blockIdx.x * 256 + threadIdx.x;     // float4 index
    const float4 p0 = ((const float4*)g_part[0])[i];
    const float4 p1 = ((const float4*)g_part[1])[i];
    const float4 p2 = ((const float4*)g_part[2])[i];
    const float sc = (float)(M_PI / 360.0);
    float4 r;
    r.x = (p0.x + p1.x + p2.x) * sc;
    r.y = (p0.y + p1.y + p2.y) * sc;
    r.z = (p0.z + p1.z + p2.z) * sc;
    r.w = (p0.w + p1.w + p2.w) * sc;
    ((float4*)out)[i] = r;
}

extern "C" void kernel_launch(void* const* d_in, const int* in_sizes, int n_in,
                              void* d_out, int out_size) {
    const float* x = (const float*)d_in[0];
    float* out = (float*)d_out;

    ramp_filter_kernel<<<NB * A, 96>>>(x);
    backproject_kernel<<<dim3(W, ASP), 256>>>();
    combine_kernel<<<(NB * W * W / 4) / 256, 256>>>(out);
}

// round 10
// speedup vs baseline: 1.3965x; 1.3965x over previous
#include <cuda_runtime.h>
#include <math.h>

#define NB    4      // batch
#define S     363    // sinogram length / recon grid
#define A     180    // angles
#define W     256    // output size
#define RP    364    // table row entries, k in [0,363]

// tab2[pair][a][k] = (mid_b0, delta_b0, mid_b1, delta_b1) for batches
// (2*pair, 2*pair+1): delta = p[k]-p[k-1], mid = p[k-1]+0.5*delta, p[-1]=p[363]=0.
// Interp at q (=pos+1, round k of q-0.5): mid + t*delta, t = (q-0.5)-k.
__device__ float4 g_tab2[2][A * RP];

// One block per (n, a) column. Spatial ramp-filter convolution, taps folded to
// immediates via full unroll:
// p[i] = 0.5*x[i] + sum_{d odd} (-2/(pi*d)^2) * (x[i-d] + x[i+d])
__global__ __launch_bounds__(384) void ramp_filter_kernel(const float* __restrict__ x) {
    const int na = blockIdx.x;
    const int n  = na / A;
    const int a  = na - n * A;

    __shared__ float xsp[S + 2 * 362];  // zeros | data | zeros
    __shared__ float ps[S + 2];         // p[-1..363], zero-padded ends

    const int t = threadIdx.x;
    if (t < 362) {
        xsp[t] = 0.0f;
        xsp[725 + t] = 0.0f;
    }
    if (t < 2) ps[t * 364] = 0.0f;      // ps[0]=p[-1]=0, ps[364]=p[363]=0
    // input layout: [n][1][s][a], a fastest
    for (int s = t; s < S; s += 384)
        xsp[362 + s] = x[(n * S + s) * A + a];
    __syncthreads();

    if (t < S) {
        const float* c = xsp + 362 + t;
        float acc = 0.5f * c[0];
        #pragma unroll
        for (int j = 0; j < 181; ++j) {
            const int d = 2 * j + 1;
            const float h = -2.0f / ((float)(M_PI * M_PI) * (float)d * (float)d);
            acc = fmaf(c[-d] + c[d], h, acc);
        }
        ps[t + 1] = acc;
    }
    __syncthreads();

    // write this batch's (mid, delta) half of the packed pair table
    float2* gr = ((float2*)&g_tab2[n >> 1][(size_t)a * RP]) + (n & 1);
    if (t < RP) {                        // k = t in [0, 363]
        const float p0 = ps[t];          // p[k-1]
        const float p1 = ps[t + 1];      // p[k]
        const float d  = p1 - p0;
        gr[2 * t] = make_float2(fmaf(0.5f, d, p0), d);
    }
}

#define CH 3                     // angles per pipeline chunk (180/3 = 60, even)
#define NCHUNK (A / CH)
#define MAGICF 12582912.0f       // 2^23 + 2^22
#define MAGICI 0x4B400000

// grid (W, 2): one block = one output row x one batch-pair; 2 batches per
// thread via ONE LDG.128 per angle. qp = xf*cos - yf*sin + 181.5;
// k = round(qp) via magic, t = qp - k in [-0.5,0.5]; value = mid + t*delta.
__global__ __launch_bounds__(256) void backproject_kernel(float* __restrict__ out) {
    const int yy = blockIdx.x;
    const int pr = blockIdx.y;
    const int xx = threadIdx.x;

    __shared__ float2 scb[A];    // (cos, 181.5 - yf*sin)

    const float yf = (float)(yy - 128);
    if (threadIdx.x < A) {
        float sn, cs;
        sincosf((float)threadIdx.x * (float)(M_PI / 180.0), &sn, &cs);
        scb[threadIdx.x] = make_float2(cs, fmaf(-yf, sn, 181.5f));
    }
    __syncthreads();

    const float xf = (float)(xx - 128);
    const float4* __restrict__ tb = g_tab2[pr];

    float accm0 = 0.f, accm1 = 0.f;
    float accd0 = 0.f, accd1 = 0.f;

    float4 va[CH], vb[CH];
    float  wa[CH], wb[CH];

    #define LOADC(c, vv, ww)                                                  \
        {                                                                     \
            const int a0 = (c) * CH;                                          \
            _Pragma("unroll")                                                 \
            for (int k = 0; k < CH; ++k) {                                    \
                const float2 cb = scb[a0 + k];                                \
                const float qp = fmaf(xf, cb.x, cb.y);   /* q - 0.5 */        \
                const float f  = qp + MAGICF;                                 \
                const float il = f - MAGICF;             /* round(qp) */      \
                ww[k] = qp - il;                         /* in [-.5,.5] */    \
                const int i = __float_as_int(f) - MAGICI;                     \
                vv[k] = __ldg(tb + (a0 + k) * RP + i);                        \
            }                                                                 \
        }

    #define ACCC(vv, ww)                                                      \
        {                                                                     \
            _Pragma("unroll")                                                 \
            for (int k = 0; k < CH; ++k) {                                    \
                accm0 += vv[k].x;                                             \
                accd0 = fmaf(ww[k], vv[k].y, accd0);                          \
                accm1 += vv[k].z;                                             \
                accd1 = fmaf(ww[k], vv[k].w, accd1);                          \
            }                                                                 \
        }

    LOADC(0, va, wa)
    LOADC(1, vb, wb)
    #pragma unroll 1
    for (int c = 0; c + 2 < NCHUNK; c += 2) {
        ACCC(va, wa)
        LOADC(c + 2, va, wa)
        ACCC(vb, wb)
        LOADC(c + 3, vb, wb)
    }
    ACCC(va, wa)
    ACCC(vb, wb)

    #undef LOADC
    #undef ACCC

    const float sc = (float)(M_PI / 360.0);
    float* o = out + ((size_t)(2 * pr) * W * W) + (size_t)yy * W + xx;
    o[0]     = (accm0 + accd0) * sc;
    o[W * W] = (accm1 + accd1) * sc;
}

extern "C" void kernel_launch(void* const* d_in, const int* in_sizes, int n_in,
                              void* d_out, int out_size) {
    const float* x = (const float*)d_in[0];
    float* out = (float*)d_out;

    ramp_filter_kernel<<<NB * A, 384>>>(x);
    backproject_kernel<<<dim3(W, 2), 256>>>(out);
}